// round 6
// baseline (speedup 1.0000x reference)
#include <cuda_runtime.h>
#include <cuda_bf16.h>
#include <math_constants.h>
#include <cstdint>

#define NH 32
#define TDIM 1024
#define SDIM 1024
#define DDIM 128
#define TS (TDIM * SDIM)

__device__ float g_A[(size_t)NH * TS];   // raw logits (QK output)
__device__ float g_B[(size_t)NH * TS];   // final probs (AV input)

// ---------------------------------------------------------------------------
// tf32 helpers
// ---------------------------------------------------------------------------
__device__ __forceinline__ uint32_t f2tf32(float f) {
    uint32_t u;
    asm("cvt.rna.tf32.f32 %0, %1;" : "=r"(u) : "f"(f));
    return u;
}

__device__ __forceinline__ void mma_tf32(float* c, const uint32_t* a, const uint32_t* b) {
    asm volatile(
        "mma.sync.aligned.m16n8k8.row.col.f32.tf32.tf32.f32 "
        "{%0,%1,%2,%3}, {%4,%5,%6,%7}, {%8,%9}, {%0,%1,%2,%3};"
        : "+f"(c[0]), "+f"(c[1]), "+f"(c[2]), "+f"(c[3])
        : "r"(a[0]), "r"(a[1]), "r"(a[2]), "r"(a[3]), "r"(b[0]), "r"(b[1]));
}

// ---------------------------------------------------------------------------
// K1: QK^T tf32 GEMM, causal tiles linearized (36 tiles/head).
// ---------------------------------------------------------------------------
#define QK_STR 68
#define QK_SMEM_BYTES (2 * 128 * QK_STR * 4)

__global__ __launch_bounds__(256) void qk_gemm(const float* __restrict__ Q,
                                               const float* __restrict__ K) {
    int i = blockIdx.x;
    int n = blockIdx.y;
    int by = 0;
    while ((by + 1) * (by + 2) / 2 <= i) by++;
    int bx = i - by * (by + 1) / 2;

    extern __shared__ uint32_t sm_qk[];
    uint32_t* Qs = sm_qk;
    uint32_t* Ks = sm_qk + 128 * QK_STR;

    const float* Qn = Q + ((size_t)n * TDIM + by * 128) * DDIM;
    const float* Kn = K + ((size_t)n * SDIM + bx * 128) * DDIM;

    int tid = threadIdx.x;
    int lane = tid & 31, warp = tid >> 5;
    int wm = warp >> 2, wn = warp & 3;
    int g = lane >> 2, tg = lane & 3;

    float acc[4][4][4] = {};

    for (int k0 = 0; k0 < DDIM; k0 += 64) {
#pragma unroll
        for (int ii = 0; ii < 8; ii++) {
            int idx = tid + ii * 256;
            int r = idx >> 4, c4 = idx & 15;
            float4 q = *(const float4*)(Qn + (size_t)r * DDIM + k0 + c4 * 4);
            float4 k = *(const float4*)(Kn + (size_t)r * DDIM + k0 + c4 * 4);
            uint32_t* qd = Qs + r * QK_STR + c4 * 4;
            uint32_t* kd = Ks + r * QK_STR + c4 * 4;
            qd[0] = f2tf32(q.x); qd[1] = f2tf32(q.y); qd[2] = f2tf32(q.z); qd[3] = f2tf32(q.w);
            kd[0] = f2tf32(k.x); kd[1] = f2tf32(k.y); kd[2] = f2tf32(k.z); kd[3] = f2tf32(k.w);
        }
        __syncthreads();

#pragma unroll
        for (int ks = 0; ks < 64; ks += 8) {
            uint32_t a[4][4], b[4][2];
#pragma unroll
            for (int mi = 0; mi < 4; mi++) {
                int rb = wm * 64 + mi * 16;
                a[mi][0] = Qs[(rb + g) * QK_STR + ks + tg];
                a[mi][1] = Qs[(rb + g + 8) * QK_STR + ks + tg];
                a[mi][2] = Qs[(rb + g) * QK_STR + ks + tg + 4];
                a[mi][3] = Qs[(rb + g + 8) * QK_STR + ks + tg + 4];
            }
#pragma unroll
            for (int ni = 0; ni < 4; ni++) {
                int nb = wn * 32 + ni * 8;
                b[ni][0] = Ks[(nb + g) * QK_STR + ks + tg];
                b[ni][1] = Ks[(nb + g) * QK_STR + ks + tg + 4];
            }
#pragma unroll
            for (int mi = 0; mi < 4; mi++)
#pragma unroll
                for (int ni = 0; ni < 4; ni++) mma_tf32(acc[mi][ni], a[mi], b[ni]);
        }
        __syncthreads();
    }

    float* Cn = g_A + (size_t)n * TS;
#pragma unroll
    for (int mi = 0; mi < 4; mi++) {
#pragma unroll
        for (int ni = 0; ni < 4; ni++) {
            int t = by * 128 + wm * 64 + mi * 16 + g;
            int s = bx * 128 + wn * 32 + ni * 8 + 2 * tg;
            *(float2*)(Cn + (size_t)t * SDIM + s)       = make_float2(acc[mi][ni][0], acc[mi][ni][1]);
            *(float2*)(Cn + (size_t)(t + 8) * SDIM + s) = make_float2(acc[mi][ni][2], acc[mi][ni][3]);
        }
    }
}

// ---------------------------------------------------------------------------
// Middle kernel: per-t CTA, 512 threads.
// P layout: [head n][s], stride 1032 floats (= 8 mod 32).
// Projection: C[m][s] = sum_n WT[m][n]*X[n][s] via m16n8k8 (W as A operand,
// persistent in regs), fp32 epilogue for k-rank2 + identity + kdd.
// ---------------------------------------------------------------------------
#define PN 1032
#define WSTR 33
#define MID_THREADS 512
// floats: P 32*1032 | WTp 32*33 | WTo 32*33 | ginv 32
#define MID_SMEM_FLOATS (32 * PN + 2 * 32 * WSTR + 32)

extern __shared__ float s_mid[];

template <bool SCALED>
__device__ __forceinline__ void do_proj(
    float* __restrict__ P, const uint32_t* __restrict__ WT,
    const float* __restrict__ ginv,
    const float* __restrict__ kw1, const float* __restrict__ kw2,
    const float* __restrict__ kdd, int len, int warp, int lane) {
    int g = lane >> 2, tg = lane & 3;

    // W A-fragments, persistent across chunks
    uint32_t wf[2][4][4];
#pragma unroll
    for (int mt = 0; mt < 2; mt++)
#pragma unroll
        for (int kt = 0; kt < 4; kt++) {
            wf[mt][kt][0] = WT[(mt * 16 + g) * WSTR + kt * 8 + tg];
            wf[mt][kt][1] = WT[(mt * 16 + g + 8) * WSTR + kt * 8 + tg];
            wf[mt][kt][2] = WT[(mt * 16 + g) * WSTR + kt * 8 + tg + 4];
            wf[mt][kt][3] = WT[(mt * 16 + g + 8) * WSTR + kt * 8 + tg + 4];
        }

    int nch = (len + 31) >> 5;
    for (int c = warp; c < nch; c += 16) {
        int s0 = c * 32;

        // --- kh rank-2 dots: lane <-> s0+lane ---
        int sl = s0 + lane;
        float kh0 = 0.f, kh1 = 0.f;
        const float4* k1r = (const float4*)(kw1 + (size_t)sl * 64);
#pragma unroll
        for (int j = 0; j < 8; j++) {
            float4 wq = k1r[j];
            float4 wk = k1r[8 + j];
            float x0 = P[(4 * j + 0) * PN + sl];
            float x1 = P[(4 * j + 1) * PN + sl];
            float x2 = P[(4 * j + 2) * PN + sl];
            float x3 = P[(4 * j + 3) * PN + sl];
            if (SCALED) {
                x0 *= ginv[4 * j + 0]; x1 *= ginv[4 * j + 1];
                x2 *= ginv[4 * j + 2]; x3 *= ginv[4 * j + 3];
            }
            kh0 += x0 * wq.x + x1 * wq.y + x2 * wq.z + x3 * wq.w;
            kh1 += x0 * wk.x + x1 * wk.y + x2 * wk.z + x3 * wk.w;
        }

        // --- head-mix MMAs: B fragments from P columns ---
        float cacc[2][4][4] = {};
#pragma unroll
        for (int kt = 0; kt < 4; kt++) {
            float gi0, gi1;
            if (SCALED) { gi0 = ginv[kt * 8 + tg]; gi1 = ginv[kt * 8 + tg + 4]; }
#pragma unroll
            for (int nt = 0; nt < 4; nt++) {
                float f0 = P[(kt * 8 + tg) * PN + s0 + nt * 8 + g];
                float f1 = P[(kt * 8 + tg + 4) * PN + s0 + nt * 8 + g];
                if (SCALED) { f0 *= gi0; f1 *= gi1; }
                uint32_t b[2] = {f2tf32(f0), f2tf32(f1)};
                mma_tf32(cacc[0][nt], wf[0][kt], b);
                mma_tf32(cacc[1][nt], wf[1][kt], b);
            }
        }

        // --- epilogue: k-rank2 + identity + kdd, write back in place ---
#pragma unroll
        for (int nt = 0; nt < 4; nt++) {
            int se0 = s0 + nt * 8 + 2 * tg;
            int se1 = se0 + 1;
            int src0 = nt * 8 + 2 * tg, src1 = src0 + 1;
            float ka0 = __shfl_sync(~0u, kh0, src0);
            float kb0 = __shfl_sync(~0u, kh0, src1);
            float ka1 = __shfl_sync(~0u, kh1, src0);
            float kb1 = __shfl_sync(~0u, kh1, src1);
#pragma unroll
            for (int mt = 0; mt < 2; mt++) {
#pragma unroll
                for (int rr = 0; rr < 2; rr++) {
                    int m = mt * 16 + g + rr * 8;
                    float x0 = P[m * PN + se0];
                    float x1 = P[m * PN + se1];
                    if (SCALED) { float gm = ginv[m]; x0 *= gm; x1 *= gm; }
                    float w20 = kw2[(size_t)se0 * 64 + m];
                    float w30 = kw2[(size_t)se0 * 64 + 32 + m];
                    float d0  = kdd[(size_t)se0 * 32 + m];
                    float w21 = kw2[(size_t)se1 * 64 + m];
                    float w31 = kw2[(size_t)se1 * 64 + 32 + m];
                    float d1  = kdd[(size_t)se1 * 32 + m];
                    float o0 = cacc[mt][nt][rr * 2 + 0] + ka0 * w20 + ka1 * w30 + x0 * (1.f + d0);
                    float o1 = cacc[mt][nt][rr * 2 + 1] + kb0 * w21 + kb1 * w31 + x1 * (1.f + d1);
                    P[m * PN + se0] = o0;
                    P[m * PN + se1] = o1;
                }
            }
        }
    }
}

__global__ __launch_bounds__(MID_THREADS, 1) void middle_kernel(
    const float* __restrict__ sw_pre,
    const float* __restrict__ qw1_pre, const float* __restrict__ qw2_pre,
    const float* __restrict__ kw1_pre, const float* __restrict__ kw2_pre,
    const float* __restrict__ qdd_pre, const float* __restrict__ kdd_pre,
    const float* __restrict__ sw_post,
    const float* __restrict__ qw1_post, const float* __restrict__ qw2_post,
    const float* __restrict__ kw1_post, const float* __restrict__ kw2_post,
    const float* __restrict__ qdd_post, const float* __restrict__ kdd_post) {
    float* P = s_mid;                               // [32][1032]
    uint32_t* WTp = (uint32_t*)(s_mid + 32 * PN);   // [32][33] tf32 bits
    uint32_t* WTo = WTp + 32 * WSTR;
    float* ginv = (float*)(WTo + 32 * WSTR);        // [32]

    int t = 1023 - blockIdx.x;   // longest rows first
    int len = t + 1;
    int len32 = (len + 31) & ~31;
    int pad = ((t >> 6) + 1) << 6;   // AV (64-chunks) reads s < pad
    int tid = threadIdx.x;
    int warp = tid >> 5, lane = tid & 31;

    // Effective per-t mixing matrices WT[m][n] = Weff[n][m] (tf32 bits).
    // Identity kept exact fp32 in the epilogue.
    for (int idx = tid; idx < 2048; idx += MID_THREADS) {
        int which = idx >> 10;
        int r = idx & 1023;
        int n = r >> 5, m = r & 31;
        const float* sw = which ? sw_post : sw_pre;
        const float* q1 = which ? qw1_post : qw1_pre;
        const float* q2 = which ? qw2_post : qw2_pre;
        const float* qd = which ? qdd_post : qdd_pre;
        float w = sw[n * 32 + m] + q1[t * 64 + n] * q2[t * 64 + m]
                + q1[t * 64 + 32 + n] * q2[t * 64 + 32 + m];
        if (n == m) w += qd[t * 32 + m];
        (which ? WTo : WTp)[m * WSTR + n] = f2tf32(w);
    }

    // Phase A: stage g_A[n][t][0..len32) -> P[n][s]  (all conflict-free)
    for (int idx = tid; idx < 32 * 256; idx += MID_THREADS) {
        int n = idx >> 8;
        int s = (idx & 255) * 4;
        if (s < len32) {
            float4 v = *(const float4*)(g_A + (size_t)n * TS + (size_t)t * SDIM + s);
            *(float4*)(P + n * PN + s) = v;
        }
    }
    __syncthreads();

    do_proj<false>(P, WTp, nullptr, kw1_pre, kw2_pre, kdd_pre, len, warp, lane);
    __syncthreads();

    // Softmax: warp per head (16 warps x 2 heads), exp left unnormalized.
    for (int h = warp; h < 32; h += 16) {
        float* row = P + h * PN;
        float mx = -CUDART_INF_F;
        for (int s = lane; s < len; s += 32) mx = fmaxf(mx, row[s]);
#pragma unroll
        for (int o = 16; o; o >>= 1) mx = fmaxf(mx, __shfl_xor_sync(~0u, mx, o));
        float Z = 0.f;
        for (int s = lane; s < len; s += 32) {
            float e = __expf(row[s] - mx);
            row[s] = e;
            Z += e;
        }
#pragma unroll
        for (int o = 16; o; o >>= 1) Z += __shfl_xor_sync(~0u, Z, o);
        if (lane == 0) ginv[h] = 1.0f / Z;
    }
    __syncthreads();

    do_proj<true>(P, WTo, ginv, kw1_post, kw2_post, kdd_post, len, warp, lane);
    __syncthreads();

    // Phase E: P[n][s] -> g_B[n][t][s], zero-fill to 64-boundary pad.
    for (int idx = tid; idx < 32 * 256; idx += MID_THREADS) {
        int n = idx >> 8;
        int s = (idx & 255) * 4;
        if (s < pad) {
            float4 v = *(const float4*)(P + n * PN + s);
            if (s     >= len) v.x = 0.f;
            if (s + 1 >= len) v.y = 0.f;
            if (s + 2 >= len) v.z = 0.f;
            if (s + 3 >= len) v.w = 0.f;
            *(float4*)(g_B + (size_t)n * TS + (size_t)t * SDIM + s) = v;
        }
    }
}

// ---------------------------------------------------------------------------
// K3: AV tf32 GEMM. t-tile 64 x d 128, s-chunks of 64, causal bound.
// ---------------------------------------------------------------------------
#define PS_STR 68
#define VS_STR 136
#define AV_SMEM_BYTES ((64 * PS_STR + 64 * VS_STR) * 4)

__global__ __launch_bounds__(256) void av_gemm(const float* __restrict__ V,
                                               float* __restrict__ out) {
    int tt = 15 - blockIdx.x;  // longest first
    int n  = blockIdx.y;

    extern __shared__ uint32_t sm_av[];
    uint32_t* Ps = sm_av;                // [64][68]
    uint32_t* Vs = sm_av + 64 * PS_STR;  // [64][136]

    const float* Pn = g_B + (size_t)n * TS + (size_t)tt * 64 * SDIM;
    const float* Vn = V + (size_t)n * SDIM * DDIM;

    int tid = threadIdx.x;
    int lane = tid & 31, warp = tid >> 5;
    int wm = warp >> 2, wn = warp & 3;
    int g = lane >> 2, tg = lane & 3;

    float acc[2][4][4] = {};
    int nchunks = tt + 1;
    for (int c = 0; c < nchunks; c++) {
        int s0 = c * 64;
#pragma unroll
        for (int i = 0; i < 4; i++) {
            int idx = tid + i * 256;
            int r = idx >> 4, c4 = idx & 15;
            float4 p = *(const float4*)(Pn + (size_t)r * SDIM + s0 + c4 * 4);
            uint32_t* pd = Ps + r * PS_STR + c4 * 4;
            pd[0] = f2tf32(p.x); pd[1] = f2tf32(p.y); pd[2] = f2tf32(p.z); pd[3] = f2tf32(p.w);
        }
#pragma unroll
        for (int i = 0; i < 8; i++) {
            int idx = tid + i * 256;
            int r = idx >> 5, c4 = idx & 31;
            float4 v = *(const float4*)(Vn + (size_t)(s0 + r) * DDIM + c4 * 4);
            uint32_t* vd = Vs + r * VS_STR + c4 * 4;
            vd[0] = f2tf32(v.x); vd[1] = f2tf32(v.y); vd[2] = f2tf32(v.z); vd[3] = f2tf32(v.w);
        }
        __syncthreads();

#pragma unroll
        for (int ks = 0; ks < 64; ks += 8) {
            uint32_t a[2][4], b[4][2];
#pragma unroll
            for (int mi = 0; mi < 2; mi++) {
                int rb = wm * 32 + mi * 16;
                a[mi][0] = Ps[(rb + g) * PS_STR + ks + tg];
                a[mi][1] = Ps[(rb + g + 8) * PS_STR + ks + tg];
                a[mi][2] = Ps[(rb + g) * PS_STR + ks + tg + 4];
                a[mi][3] = Ps[(rb + g + 8) * PS_STR + ks + tg + 4];
            }
#pragma unroll
            for (int ni = 0; ni < 4; ni++) {
                int nb = wn * 32 + ni * 8;
                b[ni][0] = Vs[(ks + tg) * VS_STR + nb + g];
                b[ni][1] = Vs[(ks + tg + 4) * VS_STR + nb + g];
            }
#pragma unroll
            for (int mi = 0; mi < 2; mi++)
#pragma unroll
                for (int ni = 0; ni < 4; ni++) mma_tf32(acc[mi][ni], a[mi], b[ni]);
        }
        __syncthreads();
    }

#pragma unroll
    for (int mi = 0; mi < 2; mi++) {
#pragma unroll
        for (int ni = 0; ni < 4; ni++) {
            int t = tt * 64 + wm * 32 + mi * 16 + g;
            int d = wn * 32 + ni * 8 + 2 * tg;
            *(float2*)(out + ((size_t)n * TDIM + t) * DDIM + d)     = make_float2(acc[mi][ni][0], acc[mi][ni][1]);
            *(float2*)(out + ((size_t)n * TDIM + t + 8) * DDIM + d) = make_float2(acc[mi][ni][2], acc[mi][ni][3]);
        }
    }
}

// ---------------------------------------------------------------------------
// Launch
// ---------------------------------------------------------------------------
extern "C" void kernel_launch(void* const* d_in, const int* in_sizes, int n_in,
                              void* d_out, int out_size) {
    const float* query = (const float*)d_in[0];
    const float* key   = (const float*)d_in[1];
    const float* value = (const float*)d_in[2];
    const float* sw_pre  = (const float*)d_in[4];
    const float* qw1_pre = (const float*)d_in[5];
    const float* qw2_pre = (const float*)d_in[6];
    const float* kw1_pre = (const float*)d_in[7];
    const float* kw2_pre = (const float*)d_in[8];
    const float* qdd_pre = (const float*)d_in[9];
    const float* kdd_pre = (const float*)d_in[10];
    const float* sw_post  = (const float*)d_in[11];
    const float* qw1_post = (const float*)d_in[12];
    const float* qw2_post = (const float*)d_in[13];
    const float* kw1_post = (const float*)d_in[14];
    const float* kw2_post = (const float*)d_in[15];
    const float* qdd_post = (const float*)d_in[16];
    const float* kdd_post = (const float*)d_in[17];
    float* out = (float*)d_out;

    size_t mid_smem = MID_SMEM_FLOATS * sizeof(float);
    cudaFuncSetAttribute(middle_kernel, cudaFuncAttributeMaxDynamicSharedMemorySize, (int)mid_smem);
    cudaFuncSetAttribute(qk_gemm, cudaFuncAttributeMaxDynamicSharedMemorySize, QK_SMEM_BYTES);
    cudaFuncSetAttribute(av_gemm, cudaFuncAttributeMaxDynamicSharedMemorySize, AV_SMEM_BYTES);

    qk_gemm<<<dim3(36, 32), 256, QK_SMEM_BYTES>>>(query, key);
    middle_kernel<<<1024, MID_THREADS, mid_smem>>>(
        sw_pre, qw1_pre, qw2_pre, kw1_pre, kw2_pre, qdd_pre, kdd_pre,
        sw_post, qw1_post, qw2_post, kw1_post, kw2_post, qdd_post, kdd_post);
    av_gemm<<<dim3(16, 32), 256, AV_SMEM_BYTES>>>(value, out);
}

// round 7
// speedup vs baseline: 1.0797x; 1.0797x over previous
#include <cuda_runtime.h>
#include <cuda_bf16.h>
#include <math_constants.h>
#include <cstdint>

#define NH 32
#define TDIM 1024
#define SDIM 1024
#define DDIM 128
#define TS (TDIM * SDIM)

__device__ float g_A[(size_t)NH * TS];   // raw logits (QK output)
__device__ float g_B[(size_t)NH * TS];   // final probs (AV input)

// ---------------------------------------------------------------------------
// tf32 helpers
// ---------------------------------------------------------------------------
__device__ __forceinline__ uint32_t f2tf32(float f) {
    uint32_t u;
    asm("cvt.rna.tf32.f32 %0, %1;" : "=r"(u) : "f"(f));
    return u;
}

__device__ __forceinline__ void mma_tf32(float* c, const uint32_t* a, const uint32_t* b) {
    asm volatile(
        "mma.sync.aligned.m16n8k8.row.col.f32.tf32.tf32.f32 "
        "{%0,%1,%2,%3}, {%4,%5,%6,%7}, {%8,%9}, {%0,%1,%2,%3};"
        : "+f"(c[0]), "+f"(c[1]), "+f"(c[2]), "+f"(c[3])
        : "r"(a[0]), "r"(a[1]), "r"(a[2]), "r"(a[3]), "r"(b[0]), "r"(b[1]));
}

// ---------------------------------------------------------------------------
// K1: QK^T tf32 GEMM, causal tiles linearized (36 tiles/head).
// ---------------------------------------------------------------------------
#define QK_STR 68
#define QK_SMEM_BYTES (2 * 128 * QK_STR * 4)

__global__ __launch_bounds__(256) void qk_gemm(const float* __restrict__ Q,
                                               const float* __restrict__ K) {
    int i = blockIdx.x;
    int n = blockIdx.y;
    int by = 0;
    while ((by + 1) * (by + 2) / 2 <= i) by++;
    int bx = i - by * (by + 1) / 2;

    extern __shared__ uint32_t sm_qk[];
    uint32_t* Qs = sm_qk;
    uint32_t* Ks = sm_qk + 128 * QK_STR;

    const float* Qn = Q + ((size_t)n * TDIM + by * 128) * DDIM;
    const float* Kn = K + ((size_t)n * SDIM + bx * 128) * DDIM;

    int tid = threadIdx.x;
    int lane = tid & 31, warp = tid >> 5;
    int wm = warp >> 2, wn = warp & 3;
    int g = lane >> 2, tg = lane & 3;

    float acc[4][4][4] = {};

    for (int k0 = 0; k0 < DDIM; k0 += 64) {
#pragma unroll
        for (int ii = 0; ii < 8; ii++) {
            int idx = tid + ii * 256;
            int r = idx >> 4, c4 = idx & 15;
            float4 q = *(const float4*)(Qn + (size_t)r * DDIM + k0 + c4 * 4);
            float4 k = *(const float4*)(Kn + (size_t)r * DDIM + k0 + c4 * 4);
            uint32_t* qd = Qs + r * QK_STR + c4 * 4;
            uint32_t* kd = Ks + r * QK_STR + c4 * 4;
            qd[0] = f2tf32(q.x); qd[1] = f2tf32(q.y); qd[2] = f2tf32(q.z); qd[3] = f2tf32(q.w);
            kd[0] = f2tf32(k.x); kd[1] = f2tf32(k.y); kd[2] = f2tf32(k.z); kd[3] = f2tf32(k.w);
        }
        __syncthreads();

#pragma unroll
        for (int ks = 0; ks < 64; ks += 8) {
            uint32_t a[4][4], b[4][2];
#pragma unroll
            for (int mi = 0; mi < 4; mi++) {
                int rb = wm * 64 + mi * 16;
                a[mi][0] = Qs[(rb + g) * QK_STR + ks + tg];
                a[mi][1] = Qs[(rb + g + 8) * QK_STR + ks + tg];
                a[mi][2] = Qs[(rb + g) * QK_STR + ks + tg + 4];
                a[mi][3] = Qs[(rb + g + 8) * QK_STR + ks + tg + 4];
            }
#pragma unroll
            for (int ni = 0; ni < 4; ni++) {
                int nb = wn * 32 + ni * 8;
                b[ni][0] = Ks[(nb + g) * QK_STR + ks + tg];
                b[ni][1] = Ks[(nb + g) * QK_STR + ks + tg + 4];
            }
#pragma unroll
            for (int mi = 0; mi < 4; mi++)
#pragma unroll
                for (int ni = 0; ni < 4; ni++) mma_tf32(acc[mi][ni], a[mi], b[ni]);
        }
        __syncthreads();
    }

    float* Cn = g_A + (size_t)n * TS;
#pragma unroll
    for (int mi = 0; mi < 4; mi++) {
#pragma unroll
        for (int ni = 0; ni < 4; ni++) {
            int t = by * 128 + wm * 64 + mi * 16 + g;
            int s = bx * 128 + wn * 32 + ni * 8 + 2 * tg;
            *(float2*)(Cn + (size_t)t * SDIM + s)       = make_float2(acc[mi][ni][0], acc[mi][ni][1]);
            *(float2*)(Cn + (size_t)(t + 8) * SDIM + s) = make_float2(acc[mi][ni][2], acc[mi][ni][3]);
        }
    }
}

// ---------------------------------------------------------------------------
// Middle kernel: per-t CTA, 1024 threads.
// P layout: head-major [n][s], stride PN=1032 (== 8 mod 32).
// Projection: C[s][m] = sum_n X[s][n] * W[n][m]:
//   A = X (from P columns; bank 8*tg+g, conflict-free)
//   B = W[n][m] stride 40 (bank 8*tg+g, conflict-free)
//   epilogue: k-rank2 + identity + kdd, fp32, no shuffles beyond tg-reduce.
// ---------------------------------------------------------------------------
#define PN 1032
#define WBS 40
#define MID_THREADS 1024
// floats: P 32*1032 | WB 2*32*40 | ginv 32
#define MID_SMEM_FLOATS (32 * PN + 2 * 32 * WBS + 32)

extern __shared__ float s_mid[];

template <bool SCALED>
__device__ __forceinline__ void do_proj(
    float* __restrict__ P, const uint32_t* __restrict__ WB,
    const float* __restrict__ ginv,
    const float* __restrict__ kw1, const float* __restrict__ kw2,
    const float* __restrict__ kdd, int len, int warp, int lane) {
    int g = lane >> 2, tg = lane & 3;

    int nch = (len + 15) >> 4;
    for (int c = warp; c < nch; c += 32) {
        int s0 = c << 4;
        int sa = s0 + g, sb = s0 + g + 8;

        // --- kh rank-2 partial dots (n staggered per tg to avoid conflicts) ---
        float kh0[2] = {0.f, 0.f}, kh1[2] = {0.f, 0.f};
#pragma unroll
        for (int j = 0; j < 8; j++) {
            int n = tg * 8 + ((j + tg) & 7);
            float gi = SCALED ? ginv[n] : 1.f;
            float x0 = P[n * PN + sa] * gi;
            float x1 = P[n * PN + sb] * gi;
            float wq0 = kw1[(size_t)sa * 64 + n];
            float wk0 = kw1[(size_t)sa * 64 + 32 + n];
            float wq1 = kw1[(size_t)sb * 64 + n];
            float wk1 = kw1[(size_t)sb * 64 + 32 + n];
            kh0[0] += x0 * wq0; kh1[0] += x0 * wk0;
            kh0[1] += x1 * wq1; kh1[1] += x1 * wk1;
        }
#pragma unroll
        for (int o = 1; o <= 2; o <<= 1) {
            kh0[0] += __shfl_xor_sync(~0u, kh0[0], o);
            kh0[1] += __shfl_xor_sync(~0u, kh0[1], o);
            kh1[0] += __shfl_xor_sync(~0u, kh1[0], o);
            kh1[1] += __shfl_xor_sync(~0u, kh1[1], o);
        }

        // --- head-mix MMAs ---
        float cacc[4][4] = {};
#pragma unroll
        for (int kt = 0; kt < 4; kt++) {
            int k0 = kt * 8;
            float gi0 = SCALED ? ginv[k0 + tg] : 1.f;
            float gi1 = SCALED ? ginv[k0 + tg + 4] : 1.f;
            uint32_t a[4];
            a[0] = f2tf32(P[(k0 + tg) * PN + sa] * gi0);
            a[1] = f2tf32(P[(k0 + tg) * PN + sb] * gi0);
            a[2] = f2tf32(P[(k0 + tg + 4) * PN + sa] * gi1);
            a[3] = f2tf32(P[(k0 + tg + 4) * PN + sb] * gi1);
#pragma unroll
            for (int nt = 0; nt < 4; nt++) {
                uint32_t b[2];
                b[0] = WB[(k0 + tg) * WBS + nt * 8 + g];
                b[1] = WB[(k0 + tg + 4) * WBS + nt * 8 + g];
                mma_tf32(cacc[nt], a, b);
            }
        }

        // --- epilogue: k-rank2 + identity + kdd, write back in place ---
#pragma unroll
        for (int nt = 0; nt < 4; nt++) {
            int m0 = nt * 8 + 2 * tg;
            int m1 = m0 + 1;
            float gm0 = SCALED ? ginv[m0] : 1.f;
            float gm1 = SCALED ? ginv[m1] : 1.f;
#pragma unroll
            for (int rr = 0; rr < 2; rr++) {
                int s = rr ? sb : sa;
                float x0 = P[m0 * PN + s] * gm0;
                float x1 = P[m1 * PN + s] * gm1;
                float2 w2 = *(const float2*)(kw2 + (size_t)s * 64 + m0);
                float2 w3 = *(const float2*)(kw2 + (size_t)s * 64 + 32 + m0);
                float2 kd = *(const float2*)(kdd + (size_t)s * 32 + m0);
                float o0 = cacc[nt][rr * 2 + 0] + kh0[rr] * w2.x + kh1[rr] * w3.x + x0 * (1.f + kd.x);
                float o1 = cacc[nt][rr * 2 + 1] + kh0[rr] * w2.y + kh1[rr] * w3.y + x1 * (1.f + kd.y);
                P[m0 * PN + s] = o0;
                P[m1 * PN + s] = o1;
            }
        }
    }
}

__global__ __launch_bounds__(MID_THREADS, 1) void middle_kernel(
    const float* __restrict__ sw_pre,
    const float* __restrict__ qw1_pre, const float* __restrict__ qw2_pre,
    const float* __restrict__ kw1_pre, const float* __restrict__ kw2_pre,
    const float* __restrict__ qdd_pre, const float* __restrict__ kdd_pre,
    const float* __restrict__ sw_post,
    const float* __restrict__ qw1_post, const float* __restrict__ qw2_post,
    const float* __restrict__ kw1_post, const float* __restrict__ kw2_post,
    const float* __restrict__ qdd_post, const float* __restrict__ kdd_post) {
    float* P = s_mid;                               // [32][1032]
    uint32_t* WBp = (uint32_t*)(s_mid + 32 * PN);   // [32][40] tf32 bits
    uint32_t* WBo = WBp + 32 * WBS;
    float* ginv = (float*)(WBo + 32 * WBS);         // [32]

    int t = 1023 - blockIdx.x;   // longest rows first
    int len = t + 1;
    int len32 = (len + 31) & ~31;
    int pad = ((t >> 6) + 1) << 6;   // AV (64-chunks) reads s < pad
    int tid = threadIdx.x;
    int warp = tid >> 5, lane = tid & 31;

    // Effective per-t mixing matrices W[n][m] (tf32 bits); identity kept fp32.
    for (int idx = tid; idx < 2048; idx += MID_THREADS) {
        int which = idx >> 10;
        int r = idx & 1023;
        int n = r >> 5, m = r & 31;
        const float* sw = which ? sw_post : sw_pre;
        const float* q1 = which ? qw1_post : qw1_pre;
        const float* q2 = which ? qw2_post : qw2_pre;
        const float* qd = which ? qdd_post : qdd_pre;
        float w = sw[n * 32 + m] + q1[t * 64 + n] * q2[t * 64 + m]
                + q1[t * 64 + 32 + n] * q2[t * 64 + 32 + m];
        if (n == m) w += qd[t * 32 + m];
        (which ? WBo : WBp)[n * WBS + m] = f2tf32(w);
    }

    // Phase A: stage g_A[n][t][0..len32) -> P[n][s] (float4, conflict-free)
    for (int idx = tid; idx < 32 * 256; idx += MID_THREADS) {
        int n = idx >> 8;
        int s = (idx & 255) * 4;
        if (s < len32) {
            float4 v = *(const float4*)(g_A + (size_t)n * TS + (size_t)t * SDIM + s);
            *(float4*)(P + n * PN + s) = v;
        }
    }
    __syncthreads();

    do_proj<false>(P, WBp, nullptr, kw1_pre, kw2_pre, kdd_pre, len, warp, lane);
    __syncthreads();

    // Softmax: warp per head (exactly 32 warps); exp left unnormalized.
    {
        float* row = P + warp * PN;
        float mx = -CUDART_INF_F;
#pragma unroll 4
        for (int s = lane; s < len; s += 32) mx = fmaxf(mx, row[s]);
#pragma unroll
        for (int o = 16; o; o >>= 1) mx = fmaxf(mx, __shfl_xor_sync(~0u, mx, o));
        float Z = 0.f;
#pragma unroll 4
        for (int s = lane; s < len; s += 32) {
            float e = __expf(row[s] - mx);
            row[s] = e;
            Z += e;
        }
#pragma unroll
        for (int o = 16; o; o >>= 1) Z += __shfl_xor_sync(~0u, Z, o);
        if (lane == 0) ginv[warp] = 1.0f / Z;
    }
    __syncthreads();

    do_proj<true>(P, WBo, ginv, kw1_post, kw2_post, kdd_post, len, warp, lane);
    __syncthreads();

    // Phase E: P[n][s] -> g_B[n][t][s], zero-fill to 64-boundary pad.
    for (int idx = tid; idx < 32 * 256; idx += MID_THREADS) {
        int n = idx >> 8;
        int s = (idx & 255) * 4;
        if (s < pad) {
            float4 v = *(const float4*)(P + n * PN + s);
            if (s     >= len) v.x = 0.f;
            if (s + 1 >= len) v.y = 0.f;
            if (s + 2 >= len) v.z = 0.f;
            if (s + 3 >= len) v.w = 0.f;
            *(float4*)(g_B + (size_t)n * TS + (size_t)t * SDIM + s) = v;
        }
    }
}

// ---------------------------------------------------------------------------
// K3: AV tf32 GEMM. t-tile 64 x d 128, s-chunks of 64, causal bound.
// ---------------------------------------------------------------------------
#define PS_STR 68
#define VS_STR 136
#define AV_SMEM_BYTES ((64 * PS_STR + 64 * VS_STR) * 4)

__global__ __launch_bounds__(256) void av_gemm(const float* __restrict__ V,
                                               float* __restrict__ out) {
    int tt = 15 - blockIdx.x;  // longest first
    int n  = blockIdx.y;

    extern __shared__ uint32_t sm_av[];
    uint32_t* Ps = sm_av;                // [64][68]
    uint32_t* Vs = sm_av + 64 * PS_STR;  // [64][136]

    const float* Pn = g_B + (size_t)n * TS + (size_t)tt * 64 * SDIM;
    const float* Vn = V + (size_t)n * SDIM * DDIM;

    int tid = threadIdx.x;
    int lane = tid & 31, warp = tid >> 5;
    int wm = warp >> 2, wn = warp & 3;
    int g = lane >> 2, tg = lane & 3;

    float acc[2][4][4] = {};
    int nchunks = tt + 1;
    for (int c = 0; c < nchunks; c++) {
        int s0 = c * 64;
#pragma unroll
        for (int i = 0; i < 4; i++) {
            int idx = tid + i * 256;
            int r = idx >> 4, c4 = idx & 15;
            float4 p = *(const float4*)(Pn + (size_t)r * SDIM + s0 + c4 * 4);
            uint32_t* pd = Ps + r * PS_STR + c4 * 4;
            pd[0] = f2tf32(p.x); pd[1] = f2tf32(p.y); pd[2] = f2tf32(p.z); pd[3] = f2tf32(p.w);
        }
#pragma unroll
        for (int i = 0; i < 8; i++) {
            int idx = tid + i * 256;
            int r = idx >> 5, c4 = idx & 31;
            float4 v = *(const float4*)(Vn + (size_t)(s0 + r) * DDIM + c4 * 4);
            uint32_t* vd = Vs + r * VS_STR + c4 * 4;
            vd[0] = f2tf32(v.x); vd[1] = f2tf32(v.y); vd[2] = f2tf32(v.z); vd[3] = f2tf32(v.w);
        }
        __syncthreads();

#pragma unroll
        for (int ks = 0; ks < 64; ks += 8) {
            uint32_t a[2][4], b[4][2];
#pragma unroll
            for (int mi = 0; mi < 2; mi++) {
                int rb = wm * 32 + mi * 16;
                a[mi][0] = Ps[(rb + g) * PS_STR + ks + tg];
                a[mi][1] = Ps[(rb + g + 8) * PS_STR + ks + tg];
                a[mi][2] = Ps[(rb + g) * PS_STR + ks + tg + 4];
                a[mi][3] = Ps[(rb + g + 8) * PS_STR + ks + tg + 4];
            }
#pragma unroll
            for (int ni = 0; ni < 4; ni++) {
                int nb = wn * 32 + ni * 8;
                b[ni][0] = Vs[(ks + tg) * VS_STR + nb + g];
                b[ni][1] = Vs[(ks + tg + 4) * VS_STR + nb + g];
            }
#pragma unroll
            for (int mi = 0; mi < 2; mi++)
#pragma unroll
                for (int ni = 0; ni < 4; ni++) mma_tf32(acc[mi][ni], a[mi], b[ni]);
        }
        __syncthreads();
    }

#pragma unroll
    for (int mi = 0; mi < 2; mi++) {
#pragma unroll
        for (int ni = 0; ni < 4; ni++) {
            int t = tt * 64 + wm * 32 + mi * 16 + g;
            int d = wn * 32 + ni * 8 + 2 * tg;
            *(float2*)(out + ((size_t)n * TDIM + t) * DDIM + d)     = make_float2(acc[mi][ni][0], acc[mi][ni][1]);
            *(float2*)(out + ((size_t)n * TDIM + t + 8) * DDIM + d) = make_float2(acc[mi][ni][2], acc[mi][ni][3]);
        }
    }
}

// ---------------------------------------------------------------------------
// Launch
// ---------------------------------------------------------------------------
extern "C" void kernel_launch(void* const* d_in, const int* in_sizes, int n_in,
                              void* d_out, int out_size) {
    const float* query = (const float*)d_in[0];
    const float* key   = (const float*)d_in[1];
    const float* value = (const float*)d_in[2];
    const float* sw_pre  = (const float*)d_in[4];
    const float* qw1_pre = (const float*)d_in[5];
    const float* qw2_pre = (const float*)d_in[6];
    const float* kw1_pre = (const float*)d_in[7];
    const float* kw2_pre = (const float*)d_in[8];
    const float* qdd_pre = (const float*)d_in[9];
    const float* kdd_pre = (const float*)d_in[10];
    const float* sw_post  = (const float*)d_in[11];
    const float* qw1_post = (const float*)d_in[12];
    const float* qw2_post = (const float*)d_in[13];
    const float* kw1_post = (const float*)d_in[14];
    const float* kw2_post = (const float*)d_in[15];
    const float* qdd_post = (const float*)d_in[16];
    const float* kdd_post = (const float*)d_in[17];
    float* out = (float*)d_out;

    size_t mid_smem = MID_SMEM_FLOATS * sizeof(float);
    cudaFuncSetAttribute(middle_kernel, cudaFuncAttributeMaxDynamicSharedMemorySize, (int)mid_smem);
    cudaFuncSetAttribute(qk_gemm, cudaFuncAttributeMaxDynamicSharedMemorySize, QK_SMEM_BYTES);
    cudaFuncSetAttribute(av_gemm, cudaFuncAttributeMaxDynamicSharedMemorySize, AV_SMEM_BYTES);

    qk_gemm<<<dim3(36, 32), 256, QK_SMEM_BYTES>>>(query, key);
    middle_kernel<<<1024, MID_THREADS, mid_smem>>>(
        sw_pre, qw1_pre, qw2_pre, kw1_pre, kw2_pre, qdd_pre, kdd_pre,
        sw_post, qw1_post, qw2_post, kw1_post, kw2_post, qdd_post, kdd_post);
    av_gemm<<<dim3(16, 32), 256, AV_SMEM_BYTES>>>(value, out);
}